// round 15
// baseline (speedup 1.0000x reference)
#include <cuda_runtime.h>
#include <cuda_bf16.h>
#include <cstdint>

#define TLEN 128
#define HID  256
#define CTXD 16

#define SBW 280                 // B row stride (bf16 units)
#define SBB 560                 // B row stride (bytes)
#define BSPL 73920              // one B split: 132 rows * 560B
#define A0_OFF 147840           // A buffer 0 (32 KB)
#define A1_OFF 180608           // A buffer 1 (32 KB)
#define SCR_OFF 213376
#define CF_OFF  215424
#define RV_OFF  215936
#define RI_OFF  215952
#define SMEM_BYTES 215968
// head overlay (A region; pipeline drained before use)
#define PA_OFF  147840          // [2][17][128] f32
#define EVW_OFF 165248          // 16x256 f32
#define SWW_OFF 181632          // 256 f32
#define EVS_OFF 182656          // 16x128 f32
#define ATT_OFF 190848          // 128 f32

#define NSTEP 320               // 64 proj + 8*32 conv, 16 k-units each
__device__ __align__(1024) unsigned char gW[(size_t)NSTEP * 16384];

__device__ __forceinline__ void mma_bf16(float* d, uint32_t a0, uint32_t a1, uint32_t a2, uint32_t a3,
                                         uint32_t b0, uint32_t b1) {
    asm("mma.sync.aligned.m16n8k16.row.col.f32.bf16.bf16.f32 "
        "{%0,%1,%2,%3}, {%4,%5,%6,%7}, {%8,%9}, {%0,%1,%2,%3};"
        : "+f"(d[0]), "+f"(d[1]), "+f"(d[2]), "+f"(d[3])
        : "r"(a0), "r"(a1), "r"(a2), "r"(a3), "r"(b0), "r"(b1));
}
__device__ __forceinline__ void split2(float w, __nv_bfloat16& hi, __nv_bfloat16& lo) {
    hi = __float2bfloat16(w);
    lo = __float2bfloat16(w - __bfloat162float(hi));
}
__device__ __forceinline__ unsigned short spc(float w, int sp) {
    __nv_bfloat16 hi = __float2bfloat16(w);
    if (sp == 0) return __bfloat16_as_ushort(hi);
    return __bfloat16_as_ushort(__float2bfloat16(w - __bfloat162float(hi)));
}
__device__ __forceinline__ int PERMC(int k) {
    int v = k & 15, p = v >> 1, bb = v & 1;
    int pos = (p < 4) ? (p << 1) : (((p - 4) << 1) + 1);
    return (k & ~15) + (pos << 1) + bb;
}

// ---------------- prep: weights -> per-lane fragment-order step images ----------------
__global__ void prep_kernel(const float* __restrict__ conv_w, const float* __restrict__ proj_w) {
    const int gs = blockIdx.x, t = threadIdx.x;
    const int lane = t & 31, sp = (t >> 5) & 1, mgq = t >> 6;
    const int gr = lane >> 2, lc = lane & 3;
    int base, l = 0, tap = 0;
    bool proj;
    if (gs < 64) { proj = true; base = gs * 16; }
    else { int tt = gs - 64; l = tt >> 5; int c = tt & 31; tap = c >> 4; base = (c & 15) * 16; proj = false; }
    for (int mgi = 0; mgi < 4; mgi++) {
        int mg = mgq * 4 + mgi;
        int m0 = mg * 16 + gr, m1 = m0 + 8;
        int c0 = base + lc * 2, c2 = c0 + 8;
        float w[8];
        if (proj) {
            w[0] = proj_w[(size_t)m0 * 1024 + c0]; w[1] = proj_w[(size_t)m0 * 1024 + c0 + 1];
            w[2] = proj_w[(size_t)m1 * 1024 + c0]; w[3] = proj_w[(size_t)m1 * 1024 + c0 + 1];
            w[4] = proj_w[(size_t)m0 * 1024 + c2]; w[5] = proj_w[(size_t)m0 * 1024 + c2 + 1];
            w[6] = proj_w[(size_t)m1 * 1024 + c2]; w[7] = proj_w[(size_t)m1 * 1024 + c2 + 1];
        } else {
            const float* cw = conv_w + (size_t)l * 256 * 256 * 2 + tap;
            w[0] = cw[((size_t)m0 * 256 + c0) * 2]; w[1] = cw[((size_t)m0 * 256 + c0 + 1) * 2];
            w[2] = cw[((size_t)m1 * 256 + c0) * 2]; w[3] = cw[((size_t)m1 * 256 + c0 + 1) * 2];
            w[4] = cw[((size_t)m0 * 256 + c2) * 2]; w[5] = cw[((size_t)m0 * 256 + c2 + 1) * 2];
            w[6] = cw[((size_t)m1 * 256 + c2) * 2]; w[7] = cw[((size_t)m1 * 256 + c2 + 1) * 2];
        }
        uint32_t u[4];
        #pragma unroll
        for (int i = 0; i < 4; i++)
            u[i] = (uint32_t)spc(w[i * 2], sp) | ((uint32_t)spc(w[i * 2 + 1], sp) << 16);
        *(uint4*)(gW + ((size_t)(gs * 16 + mg) * 2 + sp) * 512 + lane * 16) =
            make_uint4(u[0], u[1], u[2], u[3]);
    }
}

// ---------------- pipeline helpers ----------------
__device__ __forceinline__ void wait1() { asm volatile("cp.async.wait_group 1;" ::: "memory"); }
__device__ __forceinline__ void wait0() { asm volatile("cp.async.wait_group 0;" ::: "memory"); }

__device__ __forceinline__ void issue_step(uint32_t sbase, int s2, int mgbase, int warp, int lane) {
    uint32_t dst = sbase + ((s2 & 1) ? A1_OFF : A0_OFF) + (warp << 12) + (lane << 4);
    const unsigned char* src = gW + ((size_t)s2 * 16 + mgbase) * 1024 + lane * 16;
    #pragma unroll
    for (int q = 0; q < 8; q++)
        asm volatile("cp.async.cg.shared.global [%0], [%1], 16;"
                     :: "r"(dst + q * 512), "l"(src + q * 512));
    asm volatile("cp.async.commit_group;");
}

// one 16-k step. B(ih0) -> wait -> A -> issue s+2 -> hh0 -> B(ih1) hoisted -> rest
__device__ __forceinline__ void step16(
    float (&d)[4][8][4], const unsigned char* sm, uint32_t sbase,
    int s, int warp, int lane, int mgbase,
    const int* brow, int cb, int shiftB, int nv)
{
    const unsigned char* Bh = sm;
    const unsigned char* Bl = sm + BSPL;
    uint2 bh0[4], bl0[4];
    #pragma unroll
    for (int nj = 0; nj < 4; nj++) {
        if (nj < nv) {
            int bb = brow[nj] + shiftB + cb;
            bh0[nj] = *(const uint2*)(Bh + bb);
            bl0[nj] = *(const uint2*)(Bl + bb);
        }
    }
    if (s == NSTEP - 1) wait0(); else wait1();
    const unsigned char* Af = sm + ((s & 1) ? A1_OFF : A0_OFF) + (warp << 12) + (lane << 4);
    uint4 ah[4], al[4];
    #pragma unroll
    for (int mi = 0; mi < 4; mi++) {
        ah[mi] = *(const uint4*)(Af + mi * 1024);
        al[mi] = *(const uint4*)(Af + mi * 1024 + 512);
    }
    if (s + 2 < NSTEP) issue_step(sbase, s + 2, mgbase, warp, lane);

    // hh block, first half
    #pragma unroll
    for (int nj = 0; nj < 4; nj++)
        if (nj < nv)
            #pragma unroll
            for (int mi = 0; mi < 4; mi++)
                mma_bf16(d[mi][nj], ah[mi].x, ah[mi].y, ah[mi].z, ah[mi].w, bh0[nj].x, bh0[nj].y);

    // hoist second-half B loads into the MMA shadow
    uint2 bh1[4], bl1[4];
    #pragma unroll
    for (int nj = 0; nj < 4; nj++) {
        int ni = 4 + nj;
        if (ni < nv) {
            int bb = brow[ni] + shiftB + cb;
            bh1[nj] = *(const uint2*)(Bh + bb);
            bl1[nj] = *(const uint2*)(Bl + bb);
        }
    }
    #pragma unroll
    for (int nj = 0; nj < 4; nj++)
        if (nj < nv)
            #pragma unroll
            for (int mi = 0; mi < 4; mi++)
                mma_bf16(d[mi][nj], al[mi].x, al[mi].y, al[mi].z, al[mi].w, bh0[nj].x, bh0[nj].y);
    #pragma unroll
    for (int nj = 0; nj < 4; nj++)
        if (nj < nv)
            #pragma unroll
            for (int mi = 0; mi < 4; mi++)
                mma_bf16(d[mi][nj], ah[mi].x, ah[mi].y, ah[mi].z, ah[mi].w, bl0[nj].x, bl0[nj].y);
    #pragma unroll
    for (int nj = 0; nj < 4; nj++)
        if (4 + nj < nv)
            #pragma unroll
            for (int mi = 0; mi < 4; mi++)
                mma_bf16(d[mi][4 + nj], ah[mi].x, ah[mi].y, ah[mi].z, ah[mi].w, bh1[nj].x, bh1[nj].y);
    #pragma unroll
    for (int nj = 0; nj < 4; nj++)
        if (4 + nj < nv)
            #pragma unroll
            for (int mi = 0; mi < 4; mi++)
                mma_bf16(d[mi][4 + nj], al[mi].x, al[mi].y, al[mi].z, al[mi].w, bh1[nj].x, bh1[nj].y);
    #pragma unroll
    for (int nj = 0; nj < 4; nj++)
        if (4 + nj < nv)
            #pragma unroll
            for (int mi = 0; mi < 4; mi++)
                mma_bf16(d[mi][4 + nj], ah[mi].x, ah[mi].y, ah[mi].z, ah[mi].w, bl1[nj].x, bl1[nj].y);
}

// ---------------- main ----------------
__global__ __launch_bounds__(256, 1)
void Model_26147760898465_kernel(
    const float* __restrict__ x,
    const float* __restrict__ proj_b, const float* __restrict__ conv_b,
    const float* __restrict__ ev_w,  const float* __restrict__ ev_b,
    const float* __restrict__ sw_w,  const float* __restrict__ sw_b,
    float* __restrict__ out)
{
    extern __shared__ unsigned char sm[];
    __nv_bfloat16* Bhi = (__nv_bfloat16*)sm;
    __nv_bfloat16* Blo = (__nv_bfloat16*)(sm + BSPL);

    const int tid = threadIdx.x, warp = tid >> 5, lane = tid & 31;
    const int gr = lane >> 2, lc = lane & 3, b = blockIdx.x;
    const int mo = (warp & 3) * 64, to = (warp >> 2) * 64;
    const int mgbase = (warp & 3) * 4;
    const uint32_t sbase = (uint32_t)__cvta_generic_to_shared(sm);
    const int pmb = 2 * (gr & ~1) + (gr & 1);

    int brow[8];
    #pragma unroll
    for (int ni = 0; ni < 8; ni++) brow[ni] = (to + ni * 8 + gr) * SBB + lc * 8;

    issue_step(sbase, 0, mgbase, warp, lane);
    issue_step(sbase, 1, mgbase, warp, lane);

    for (int i = tid; i < 4 * SBW; i += 256) {
        Bhi[128 * SBW + i] = __float2bfloat16(0.f);
        Blo[128 * SBW + i] = __float2bfloat16(0.f);
    }

    float d[4][8][4];
    #pragma unroll
    for (int mi = 0; mi < 4; mi++)
        #pragma unroll
        for (int ni = 0; ni < 8; ni++)
            #pragma unroll
            for (int r = 0; r < 4; r++) d[mi][ni][r] = 0.f;

    // ======== projection ========
    for (int p = 0; p < 4; p++) {
        __syncthreads();
        {
            int cp = tid & 127, th = tid >> 7;
            int p7 = cp & 7;
            int widx = (cp & ~7) + (p7 < 4 ? 2 * p7 : 2 * (p7 - 4) + 1);
            const float* xp0 = x + ((size_t)b * 1024 + p * 256 + cp * 2) * TLEN;
            const float* xp1 = xp0 + TLEN;
            for (int q = 0; q < 16; q++) {
                int t = th * 64 + q * 4;
                float4 v0 = *(const float4*)(xp0 + t);
                float4 v1 = *(const float4*)(xp1 + t);
                float a0[4] = {v0.x, v0.y, v0.z, v0.w};
                float a1[4] = {v1.x, v1.y, v1.z, v1.w};
                #pragma unroll
                for (int j = 0; j < 4; j++) {
                    __nv_bfloat16 h0, l0, h1, l1;
                    split2(a0[j], h0, l0); split2(a1[j], h1, l1);
                    ((uint32_t*)Bhi)[(t + j) * (SBW / 2) + widx] =
                        (uint32_t)__bfloat16_as_ushort(h0) | ((uint32_t)__bfloat16_as_ushort(h1) << 16);
                    ((uint32_t*)Blo)[(t + j) * (SBW / 2) + widx] =
                        (uint32_t)__bfloat16_as_ushort(l0) | ((uint32_t)__bfloat16_as_ushort(l1) << 16);
                }
            }
        }
        __syncthreads();
        for (int q = 0; q < 16; q++)
            step16(d, sm, sbase, p * 16 + q, warp, lane, mgbase, brow, q * 32, 0, 8);
    }
    __syncthreads();
    {
        float bias[4][2];
        #pragma unroll
        for (int mi = 0; mi < 4; mi++) {
            bias[mi][0] = __ldg(proj_b + mo + mi * 16 + gr);
            bias[mi][1] = __ldg(proj_b + mo + mi * 16 + gr + 8);
        }
        #pragma unroll
        for (int mi = 0; mi < 4; mi++)
            #pragma unroll
            for (int ni = 0; ni < 8; ni++)
                #pragma unroll
                for (int r = 0; r < 4; r++) {
                    int rb = r >> 1;
                    int ms = mo + mi * 16 + pmb + 2 * rb;
                    int t = to + ni * 8 + lc * 2 + (r & 1);
                    float y = d[mi][ni][r] + bias[mi][rb];
                    __nv_bfloat16 hi, lo; split2(y, hi, lo);
                    Bhi[t * SBW + ms] = hi; Blo[t * SBW + ms] = lo;
                }
        __syncthreads();
    }

    // ======== 8 conv layers ========
    const int DILS[8] = {1, 2, 4, 8, 16, 32, 64, 1};
    for (int l = 0; l < 8; l++) {
        const int D = DILS[l];
        // bias loads hoisted: latency hides under the 32-step loop
        float bias[4][2];
        #pragma unroll
        for (int mi = 0; mi < 4; mi++) {
            bias[mi][0] = __ldg(conv_b + l * HID + mo + mi * 16 + gr);
            bias[mi][1] = __ldg(conv_b + l * HID + mo + mi * 16 + gr + 8);
        }
        #pragma unroll
        for (int mi = 0; mi < 4; mi++)
            #pragma unroll
            for (int ni = 0; ni < 8; ni++)
                #pragma unroll
                for (int r = 0; r < 4; r++) d[mi][ni][r] = 0.f;

        const int s0 = 64 + l * 32;
        int nvD = 8;
        if (D >= 8) { int nn = (128 - D - to) >> 3; nvD = nn < 0 ? 0 : (nn > 8 ? 8 : nn); }

        for (int c = 0; c < 16; c++)
            step16(d, sm, sbase, s0 + c, warp, lane, mgbase, brow, c * 32, 0, 8);
        if (nvD == 8) {
            for (int c = 0; c < 16; c++)
                step16(d, sm, sbase, s0 + 16 + c, warp, lane, mgbase, brow, c * 32, D * SBB, 8);
        } else {
            for (int c = 0; c < 16; c++)
                step16(d, sm, sbase, s0 + 16 + c, warp, lane, mgbase, brow, c * 32, D * SBB, nvD);
        }

        // prefetch head weights during the LAST conv layer epilogue window
        if (l == 7) {
            float* evw = (float*)(sm + EVW_OFF);
            float* sww = (float*)(sm + SWW_OFF);
            for (int i = tid; i < CTXD * HID; i += 256) {
                int cc = i >> 8, k = i & 255;
                evw[cc * HID + PERMC(k)] = __ldg(ev_w + i);
            }
            sww[PERMC(tid)] = __ldg(sw_w + tid);
        }

        float* scr = (float*)(sm + SCR_OFF);
        float* colfac = (float*)(sm + CF_OFF);
        float ps[8][2];
        #pragma unroll
        for (int ni = 0; ni < 8; ni++) { ps[ni][0] = 0.f; ps[ni][1] = 0.f; }
        #pragma unroll
        for (int mi = 0; mi < 4; mi++)
            #pragma unroll
            for (int ni = 0; ni < 8; ni++)
                #pragma unroll
                for (int r = 0; r < 4; r++) {
                    int rb = r >> 1;
                    int ms = mo + mi * 16 + pmb + 2 * rb;
                    int t = to + ni * 8 + lc * 2 + (r & 1);
                    float y = d[mi][ni][r] + bias[mi][rb];
                    y = (y > 0.f) ? y : 0.2f * y;
                    y += __bfloat162float(Bhi[t * SBW + ms]) + __bfloat162float(Blo[t * SBW + ms]);
                    d[mi][ni][r] = y;
                    ps[ni][r & 1] = fmaf(y, y, ps[ni][r & 1]);
                }
        #pragma unroll
        for (int ni = 0; ni < 8; ni++)
            #pragma unroll
            for (int j = 0; j < 2; j++) {
                float v = ps[ni][j];
                v += __shfl_down_sync(0xffffffffu, v, 16);
                v += __shfl_down_sync(0xffffffffu, v, 8);
                v += __shfl_down_sync(0xffffffffu, v, 4);
                ps[ni][j] = v;
            }
        if (lane < 4) {
            #pragma unroll
            for (int ni = 0; ni < 8; ni++)
                #pragma unroll
                for (int j = 0; j < 2; j++)
                    scr[(warp & 3) * 128 + to + ni * 8 + lane * 2 + j] = ps[ni][j];
        }
        __syncthreads();
        if (tid < TLEN) {
            float s = scr[tid] + scr[128 + tid] + scr[256 + tid] + scr[384 + tid];
            colfac[tid] = 1.0f / (sqrtf(s) + 1e-8f);
        }
        __syncthreads();
        float cf[8][2];
        #pragma unroll
        for (int ni = 0; ni < 8; ni++) {
            cf[ni][0] = colfac[to + ni * 8 + lc * 2];
            cf[ni][1] = colfac[to + ni * 8 + lc * 2 + 1];
        }
        #pragma unroll
        for (int mi = 0; mi < 4; mi++)
            #pragma unroll
            for (int ni = 0; ni < 8; ni++)
                #pragma unroll
                for (int r = 0; r < 4; r++) {
                    int rb = r >> 1;
                    int ms = mo + mi * 16 + pmb + 2 * rb;
                    int t = to + ni * 8 + lc * 2 + (r & 1);
                    float y = d[mi][ni][r] * cf[ni][r & 1];
                    __nv_bfloat16 hi, lo; split2(y, hi, lo);
                    Bhi[t * SBW + ms] = hi; Blo[t * SBW + ms] = lo;
                }
        __syncthreads();
    }

    // ======== heads (ev/sw weights already staged) ========
    float* pa   = (float*)(sm + PA_OFF);
    float* evw  = (float*)(sm + EVW_OFF);
    float* sww  = (float*)(sm + SWW_OFF);
    float* evs  = (float*)(sm + EVS_OFF);
    float* attn = (float*)(sm + ATT_OFF);
    float* redv = (float*)(sm + RV_OFF);
    int*   redi = (int*)(sm + RI_OFF);
    {
        int t = tid >> 1, hf = tid & 1;
        float a[CTXD + 1];
        #pragma unroll
        for (int cc = 0; cc <= CTXD; cc++) a[cc] = 0.f;
        int i0 = hf * 128;
        for (int i = i0; i < i0 + 128; i++) {
            float hv = __bfloat162float(Bhi[t * SBW + i]) + __bfloat162float(Blo[t * SBW + i]);
            #pragma unroll
            for (int cc = 0; cc < CTXD; cc++) a[cc] = fmaf(evw[cc * HID + i], hv, a[cc]);
            a[CTXD] = fmaf(sww[i], hv, a[CTXD]);
        }
        #pragma unroll
        for (int cc = 0; cc <= CTXD; cc++) pa[(hf * 17 + cc) * 128 + t] = a[cc];
    }
    __syncthreads();
    if (tid < TLEN) {
        #pragma unroll
        for (int cc = 0; cc < CTXD; cc++)
            evs[cc * TLEN + tid] = pa[cc * 128 + tid] + pa[(17 + cc) * 128 + tid] + __ldg(ev_b + cc);
        float sw = pa[16 * 128 + tid] + pa[33 * 128 + tid] + __ldg(sw_b);
        attn[tid] = fmaxf(sw, 0.f);
    }
    __syncthreads();
    if (tid < TLEN) {
        float v = attn[tid]; int idx = tid;
        #pragma unroll
        for (int off = 16; off > 0; off >>= 1) {
            float ov = __shfl_down_sync(0xffffffffu, v, off);
            int   oi = __shfl_down_sync(0xffffffffu, idx, off);
            if (ov > v || (ov == v && oi < idx)) { v = ov; idx = oi; }
        }
        if (lane == 0) { redv[warp] = v; redi[warp] = idx; }
    }
    __syncthreads();
    if (tid == 0) {
        float v = redv[0]; int idx = redi[0];
        for (int w = 1; w < 4; w++)
            if (redv[w] > v || (redv[w] == v && redi[w] < idx)) { v = redv[w]; idx = redi[w]; }
        redv[0] = v; redi[0] = idx;
    }
    __syncthreads();
    const int bi = redi[0]; const float bv = redv[0];
    if (tid < CTXD) out[(size_t)b * CTXD + tid] = evs[tid * TLEN + bi];
    if (tid < TLEN) out[(size_t)gridDim.x * CTXD + (size_t)b * TLEN + tid] = (tid == bi) ? bv : 0.f;
}

extern "C" void kernel_launch(void* const* d_in, const int* in_sizes, int n_in,
                              void* d_out, int out_size)
{
    const float* x      = (const float*)d_in[0];
    const float* proj_w = (const float*)d_in[1];
    const float* proj_b = (const float*)d_in[2];
    const float* conv_w = (const float*)d_in[3];
    const float* conv_b = (const float*)d_in[4];
    const float* ev_w   = (const float*)d_in[5];
    const float* ev_b   = (const float*)d_in[6];
    const float* sw_w   = (const float*)d_in[7];
    const float* sw_b   = (const float*)d_in[8];
    float* out = (float*)d_out;
    const int B = in_sizes[0] / (1024 * TLEN);   // 256

    prep_kernel<<<NSTEP, 256>>>(conv_w, proj_w);
    cudaFuncSetAttribute(Model_26147760898465_kernel,
                         cudaFuncAttributeMaxDynamicSharedMemorySize, SMEM_BYTES);
    Model_26147760898465_kernel<<<B, 256, SMEM_BYTES>>>(
        x, proj_b, conv_b, ev_w, ev_b, sw_w, sw_b, out);
}